// round 1
// baseline (speedup 1.0000x reference)
#include <cuda_runtime.h>

// out[b,w] = sum_{t=0}^{63} dk[b, w+t-31] * k[b,t],  k = irf / max(irf, axis=1)
// B = 16384 rows, W = 2048, T = 64. One block per row.

#define WLEN 2048
#define TLEN 64
#define NTHREADS 256

// Logical padded row Af[i] = dk[i-31] for i in [31, 31+2048), else 0.
// Af length 2111 -> 1056 float2 logical. Pitch-pad at float2 granularity:
// storage index p(m) = m + (m>>3)  (one float2 of pad per 8 float2 = per 64B).
#define NF2      1056
#define NF2_PAD  1188   // 1056 + 1056/8 = 1188

typedef unsigned long long u64;

__device__ __forceinline__ int padi(int m) { return m + (m >> 3); }

__device__ __forceinline__ u64 fma2(u64 a, u64 b, u64 c) {
    u64 d;
    asm("fma.rn.f32x2 %0, %1, %2, %3;" : "=l"(d) : "l"(a), "l"(b), "l"(c));
    return d;
}

// Output staging swizzle (kills 16-way STS conflict, keeps float4 contiguity:
// only bits 3..4 are XORed, bits 0..2 untouched).
__device__ __forceinline__ int oswz(int w) { return w ^ (((w >> 5) & 3) << 3); }

__global__ __launch_bounds__(NTHREADS)
void irf_reconv_kernel(const float* __restrict__ dk,
                       const float* __restrict__ irf,
                       float* __restrict__ out) {
    __shared__ __align__(16) float sA[NF2_PAD * 2];   // Af, pitch-padded
    __shared__ __align__(16) float sB[NF2_PAD * 2];   // Bf[j] = Af[j+1], pitch-padded
    __shared__ __align__(16) float sK[TLEN];
    __shared__ __align__(16) float sOut[WLEN];

    const int b   = blockIdx.x;
    const int tid = threadIdx.x;

    // ---- zero padded arrays (halo regions must be 0) ----
    #pragma unroll 4
    for (int i = tid; i < NF2_PAD * 2; i += NTHREADS) { sA[i] = 0.0f; sB[i] = 0.0f; }

    // ---- normalize kernel: k = irf / max(irf) ----
    if (tid < 32) {
        float a0 = irf[(size_t)b * TLEN + 2 * tid];
        float a1 = irf[(size_t)b * TLEN + 2 * tid + 1];
        float m = fmaxf(a0, a1);
        #pragma unroll
        for (int o = 16; o > 0; o >>= 1)
            m = fmaxf(m, __shfl_xor_sync(0xffffffffu, m, o));
        sK[2 * tid]     = a0 / m;
        sK[2 * tid + 1] = a1 / m;
    }
    __syncthreads();   // zeros + sK visible before interior fill / compute

    // ---- fill interior of both copies (one global read, two smem writes) ----
    #pragma unroll 2
    for (int f = tid; f < WLEN; f += NTHREADS) {
        float v = dk[(size_t)b * WLEN + f];
        int ia = f + 31;   // Af[ia] = dk[f]
        int ib = f + 30;   // Bf[ib] = Af[ib+1] = dk[f]
        sA[(padi(ia >> 1) << 1) | (ia & 1)] = v;
        sB[(padi(ib >> 1) << 1) | (ib & 1)] = v;
    }
    __syncthreads();

    // ---- main compute ----
    // threads [0,128): even outputs w = 16j + 2i       (read copy A)
    // threads [128,256): odd outputs w = 16j + 2i + 1  (read copy B)
    // For output pair-base u = 8j + i and tap-pair s:
    //   x2 = (Af[w+2s], Af[w+2s+1]) = float2 at logical index u + s in its copy.
    //   acc2 += x2 * (k[2s], k[2s+1]); final out = acc2.lo + acc2.hi
    const float* X = (tid < 128) ? sA : sB;
    const int j    = tid & 127;
    const int base = 8 * j;

    u64 acc[8];
    #pragma unroll
    for (int i = 0; i < 8; i++) acc[i] = 0ull;

    u64 v[8];   // rolling window: v[(s+i)&7] = X2[base + s + i]
    #pragma unroll
    for (int i = 0; i < 8; i++)
        v[i] = *(const u64*)&X[padi(base + i) << 1];

    const u64* K2 = (const u64*)sK;

    #pragma unroll
    for (int s = 0; s < 32; s++) {
        u64 kk = K2[s];
        #pragma unroll
        for (int i = 0; i < 8; i++)
            acc[i] = fma2(v[(s + i) & 7], kk, acc[i]);
        // slide window: drop oldest, load X2[base + s + 8]
        v[s & 7] = *(const u64*)&X[padi(base + 8 + s) << 1];
    }

    // ---- reduce pairs, stage to shared ----
    const int wbase = 16 * j + ((tid < 128) ? 0 : 1);
    #pragma unroll
    for (int i = 0; i < 8; i++) {
        float lo, hi;
        asm("mov.b64 {%0, %1}, %2;" : "=f"(lo), "=f"(hi) : "l"(acc[i]));
        sOut[oswz(wbase + 2 * i)] = lo + hi;
    }
    __syncthreads();

    // ---- coalesced float4 store ----
    float4* og = (float4*)(out + (size_t)b * WLEN);
    #pragma unroll
    for (int r = 0; r < 2; r++) {
        int w0 = 8 * tid + 4 * r;                 // oswz constant over [w0, w0+3]
        og[w0 >> 2] = *(const float4*)&sOut[oswz(w0)];
    }
}

extern "C" void kernel_launch(void* const* d_in, const int* in_sizes, int n_in,
                              void* d_out, int out_size) {
    const float* dk  = (const float*)d_in[0];
    const float* irf = (const float*)d_in[1];
    float* out = (float*)d_out;
    int B = in_sizes[1] / TLEN;   // irf has B*64 elements
    irf_reconv_kernel<<<B, NTHREADS>>>(dk, irf, out);
}

// round 2
// speedup vs baseline: 1.6911x; 1.6911x over previous
#include <cuda_runtime.h>

// out[b,w] = sum_{t=0}^{63} dk[b, w+t-31] * k[b,t],  k = irf / max(irf, axis=1)
// B = 16384, W = 2048, T = 64. One block (128 threads) per row; 16 outputs/thread.
//
// Padded row Af[i] = dk[i-31] for i in [31, 2079), 0 elsewhere; scalars 0..2111.
// Float2 view A2[m] = (Af[2m], Af[2m+1]), m in [0,1056). Shared storage is
// pitch-padded at float2 granularity: p(m) = m + (m>>3)  (9 float2 per 8 logical
// -> 72B lane stride, conflict-free LDS.64 since 9 is coprime with 16).
//
// Even outputs w=16j+2i:   outE = sum_s A2[8j+i+s]   . (k[2s],  k[2s+1])    s=0..31
// Odd  outputs w=16j+2i+1: outO = Af[w]k0
//                               + sum_s A2[8j+i+1+s] . (k[2s+1],k[2s+2])    s=0..30
//                               + Af[w+63]k63
// Both parities share one rolling 8-deep float2 register window (40 LDS.64 total).

#define WLEN 2048
#define TLEN 64
#define NTH  128
#define NF2PAD 1188   // p(1055)+1 = 1187 -> round to 1188 float2

typedef unsigned long long u64;

__device__ __forceinline__ u64 fma2(u64 a, u64 b, u64 c) {
    u64 d;
    asm("fma.rn.f32x2 %0, %1, %2, %3;" : "=l"(d) : "l"(a), "l"(b), "l"(c));
    return d;
}
__device__ __forceinline__ void unpk(u64 a, float& x, float& y) {
    asm("mov.b64 {%0, %1}, %2;" : "=f"(x), "=f"(y) : "l"(a));
}

__global__ __launch_bounds__(NTH)
void irf_reconv_kernel(const float* __restrict__ dk,
                       const float* __restrict__ irf,
                       float* __restrict__ out) {
    __shared__ __align__(16) float sA[NF2PAD * 2];
    __shared__ __align__(16) float sK[64];    // k pairs:        K2[s]  = (k[2s],   k[2s+1])
    __shared__ __align__(16) float sKo[64];   // shifted pairs:  K2o[s] = (k[2s+1], k[2s+2]), K2o[31]=0

    const int b   = blockIdx.x;
    const int tid = threadIdx.x;

    // ---- normalize kernel (warp 0) ----
    if (tid < 32) {
        float a0 = irf[(size_t)b * TLEN + 2 * tid];
        float a1 = irf[(size_t)b * TLEN + 2 * tid + 1];
        float m = fmaxf(a0, a1);
        #pragma unroll
        for (int o = 16; o > 0; o >>= 1)
            m = fmaxf(m, __shfl_xor_sync(0xffffffffu, m, o));
        sK[2 * tid]     = a0 / m;
        sK[2 * tid + 1] = a1 / m;
    }
    // ---- zero halos only: scalars 0..30 and 2079..2111 (64 total) ----
    if (tid < 64) {
        int idx = (tid < 31) ? tid : 2079 + (tid - 31);
        int m = idx >> 1;
        sA[(m + (m >> 3)) * 2 + (idx & 1)] = 0.0f;
    }
    __syncthreads();

    // ---- fill interior (coalesced float4 LDG, scalar STS with pad map) ----
    {
        const float4* drow = (const float4*)(dk + (size_t)b * WLEN);
        #pragma unroll
        for (int t = 0; t < 4; t++) {
            int q = tid + t * NTH;           // float4 index 0..511
            float4 d = drow[q];
            int f = 4 * q;
            float vals[4] = {d.x, d.y, d.z, d.w};
            #pragma unroll
            for (int e = 0; e < 4; e++) {
                int ia = f + e + 31;         // Af index
                int m = ia >> 1;
                sA[(m + (m >> 3)) * 2 + (ia & 1)] = vals[e];
            }
        }
    }
    // ---- build shifted kernel (reads sK, visible after first sync) ----
    if (tid < 31) { sKo[2 * tid] = sK[2 * tid + 1]; sKo[2 * tid + 1] = sK[2 * tid + 2]; }
    if (tid == 31) { sKo[62] = 0.0f; sKo[63] = 0.0f; }
    __syncthreads();

    // ---- main compute: thread j owns w = 16j .. 16j+15 ----
    const int j = tid;
    const float* base9 = sA + 18 * j;        // storage addr of A2[8j]  (p(8j)=9j)

    u64 v[8];                                 // ring: v[m&7] = A2[8j+m]
    #pragma unroll
    for (int i = 0; i < 8; i++)
        v[i] = *(const u64*)(base9 + 2 * i);

    const float k0 = sK[0], k63 = sK[63];
    float bl[8];                              // Af[w]*k0 boundary for odd outputs
    #pragma unroll
    for (int i = 0; i < 8; i++) { float x, y; unpk(v[i], x, y); bl[i] = y * k0; }

    u64 accE[8], accO[8];
    #pragma unroll
    for (int i = 0; i < 8; i++) { accE[i] = 0ull; accO[i] = 0ull; }

    #pragma unroll
    for (int q = 0; q < 16; q++) {
        ulonglong2 kE = *(const ulonglong2*)&sK[4 * q];    // K2[2q], K2[2q+1]  (broadcast LDS.128)
        ulonglong2 kO = *(const ulonglong2*)&sKo[4 * q];   // K2o[2q], K2o[2q+1]
        #pragma unroll
        for (int h = 0; h < 2; h++) {
            const int s = 2 * q + h;
            const u64 kkE = h ? kE.y : kE.x;
            const u64 kkO = h ? kO.y : kO.x;
            // even taps: window currently holds A2[8j+s .. 8j+s+7]
            #pragma unroll
            for (int i = 0; i < 8; i++)
                accE[i] = fma2(v[(s + i) & 7], kkE, accE[i]);
            // slide: bring in A2[8j+8+s]   (p(8j+8+s) = 9j + 9 + s + (s>>3))
            v[s & 7] = *(const u64*)(base9 + 2 * (9 + s + (s >> 3)));
            // odd taps: window now holds A2[8j+s+1 .. 8j+s+8]
            #pragma unroll
            for (int i = 0; i < 8; i++)
                accO[i] = fma2(v[(s + 1 + i) & 7], kkO, accO[i]);
        }
    }
    // after loop the window holds A2[8j+32 .. 8j+39]: v[i] = A2[8j+32+i]

    // ---- epilogue: pack (even, odd) pairs, direct STG.128 ----
    float4* orow = (float4*)(out + (size_t)b * WLEN + 16 * j);
    #pragma unroll
    for (int p = 0; p < 4; p++) {
        float4 r;
        {
            const int i = 2 * p;
            float ex, ey, ox, oy, hx, hy;
            unpk(accE[i], ex, ey); unpk(accO[i], ox, oy); unpk(v[i], hx, hy);
            r.x = ex + ey;
            r.y = (ox + oy) + bl[i] + hx * k63;   // + Af[w+63]*k63
        }
        {
            const int i = 2 * p + 1;
            float ex, ey, ox, oy, hx, hy;
            unpk(accE[i], ex, ey); unpk(accO[i], ox, oy); unpk(v[i], hx, hy);
            r.z = ex + ey;
            r.w = (ox + oy) + bl[i] + hx * k63;
        }
        orow[p] = r;
    }
}

extern "C" void kernel_launch(void* const* d_in, const int* in_sizes, int n_in,
                              void* d_out, int out_size) {
    const float* dk  = (const float*)d_in[0];
    const float* irf = (const float*)d_in[1];
    float* out = (float*)d_out;
    int B = in_sizes[1] / TLEN;   // irf has B*64 elements
    irf_reconv_kernel<<<B, NTH>>>(dk, irf, out);
}

// round 3
// speedup vs baseline: 1.8280x; 1.0809x over previous
#include <cuda_runtime.h>

// out[b,w] = sum_{t=0}^{63} dk[b, w+t-31] * k[b,t],  k = irf / max(irf, axis=1)
// B = 16384, W = 2048, T = 64. One block (128 threads) per row; 16 outputs/thread.
//
// Layout: Af[i] = dk[i-32] for i in [32,2080), 0 elsewhere (even shift so dk
// float2 pairs align with A2 pairs). A2[m] = (Af[2m], Af[2m+1]).
// Storage pitch-pad: p(m) = m + (m>>3)  (9 float2 stored per 8 logical; lane
// stride 72B -> conflict-free 2-wavefront LDS.64).
//
// out[w] = sum_t Af[w+1+t] * k[t]:
//   odd  w=2u+1: Σ_{s=0..31} A2[u+1+s] . K2[s],   K2[s]  = (k[2s],   k[2s+1])
//   even w=2u  : Af[2u+1]k0 + Σ_{s=0..30} A2[u+1+s] . K2o[s] + Af[2u+64]k63
//                K2o[s] = (k[2s+1], k[2s+2]),  K2o[31] = (0,0)
//
// Mainloop: 12-deep register ring, 2 taps/iter, prefetch 2 positions one full
// iteration ahead (LDS latency 29cyc hidden behind 32 FFMA2 = 64 pipe cyc).

#define WLEN 2048
#define TLEN 64
#define NTH  128
#define NF2PAD 1190   // p(1057) = 1189 -> 1190 float2 = 9520 B

typedef unsigned long long u64;

__device__ __forceinline__ u64 fma2(u64 a, u64 b, u64 c) {
    u64 d;
    asm("fma.rn.f32x2 %0, %1, %2, %3;" : "=l"(d) : "l"(a), "l"(b), "l"(c));
    return d;
}
__device__ __forceinline__ void unpk(u64 a, float& x, float& y) {
    asm("mov.b64 {%0, %1}, %2;" : "=f"(x), "=f"(y) : "l"(a));
}

__global__ __launch_bounds__(NTH)
void irf_reconv_kernel(const float* __restrict__ dk,
                       const float* __restrict__ irf,
                       float* __restrict__ out) {
    __shared__ __align__(16) float sA[NF2PAD * 2];
    __shared__ __align__(16) float sK[64];    // K2[s]  = (k[2s], k[2s+1])
    __shared__ __align__(16) float sKo[64];   // K2o[s] = (k[2s+1], k[2s+2]); K2o[31]=(0,0)

    const int b   = blockIdx.x;
    const int tid = threadIdx.x;
    float2* s2 = (float2*)sA;

    // ---- warp 0: normalize kernel + build shifted copy, all in registers ----
    if (tid < 32) {
        float a0 = irf[(size_t)b * TLEN + 2 * tid];
        float a1 = irf[(size_t)b * TLEN + 2 * tid + 1];
        float m = fmaxf(a0, a1);
        #pragma unroll
        for (int o = 16; o > 0; o >>= 1)
            m = fmaxf(m, __shfl_xor_sync(0xffffffffu, m, o));
        float r = 1.0f / m;
        float k0v = a0 * r, k1v = a1 * r;
        // exactness vs reference (irf/max): use division to match bitwise-ish
        k0v = a0 / m; k1v = a1 / m;
        sK[2 * tid]     = k0v;
        sK[2 * tid + 1] = k1v;
        float nxt = __shfl_down_sync(0xffffffffu, k0v, 1);   // k[2t+2]
        bool last = (tid == 31);
        sKo[2 * tid]     = last ? 0.0f : k1v;
        sKo[2 * tid + 1] = last ? 0.0f : nxt;
    }

    // ---- zero halo: A2[0..15] and A2[1040..1057] (34 float2) ----
    if (tid < 34) {
        int m = (tid < 16) ? tid : (1040 + tid - 16);
        s2[m + (m >> 3)] = make_float2(0.0f, 0.0f);
    }

    // ---- fill interior: coalesced LDG.128, pair-contiguous STS.64 ----
    {
        const float4* drow = (const float4*)(dk + (size_t)b * WLEN);
        #pragma unroll
        for (int t = 0; t < 4; t++) {
            int q = tid + t * NTH;            // 0..511
            float4 d = drow[q];
            int m0 = 2 * q + 16;              // even, m0%8 != 7 -> pair contiguous
            int p0 = m0 + (m0 >> 3);
            s2[p0]     = make_float2(d.x, d.y);
            s2[p0 + 1] = make_float2(d.z, d.w);
        }
    }
    __syncthreads();

    // ---- main compute: thread j owns u = 8j+i  (w = 16j+2i, 16j+2i+1) ----
    const int j = tid;
    const float* base = sA + 18 * j;          // &storage of A2[8j]; pos m at
                                              // float offset 2*(m + (m>>3))
    #define LD2(m) (*(const u64*)(base + 2 * ((m) + ((m) >> 3))))

    u64 v[12];                                 // v[m % 12] = A2[8j + m]
    #pragma unroll
    for (int m = 0; m < 10; m++) v[m] = LD2(m);

    const float k0  = sK[0];
    const float k63 = sK[63];

    float bl[8];                               // hi(A2[8j+i]) * k0  (even boundary)
    #pragma unroll
    for (int i = 0; i < 8; i++) { float x, y; unpk(v[i], x, y); bl[i] = y * k0; }

    u64 accE[8], accO[8];
    #pragma unroll
    for (int i = 0; i < 8; i++) { accE[i] = 0ull; accO[i] = 0ull; }

    #pragma unroll
    for (int sp = 0; sp < 16; sp++) {
        // prefetch positions 2sp+10, 2sp+11 (consumed next iteration)
        v[(2 * sp + 10) % 12] = LD2(2 * sp + 10);
        v[(2 * sp + 11) % 12] = LD2(2 * sp + 11);

        ulonglong2 kE = *(const ulonglong2*)&sK [4 * sp];  // K2[2sp], K2[2sp+1]
        ulonglong2 kO = *(const ulonglong2*)&sKo[4 * sp];  // K2o[2sp], K2o[2sp+1]

        #pragma unroll
        for (int i = 0; i < 8; i++) {          // tap s0 = 2sp: positions 2sp+1+i
            u64 x = v[(2 * sp + 1 + i) % 12];
            accO[i] = fma2(x, kE.x, accO[i]);
            accE[i] = fma2(x, kO.x, accE[i]);
        }
        #pragma unroll
        for (int i = 0; i < 8; i++) {          // tap s1 = 2sp+1: positions 2sp+2+i
            u64 x = v[(2 * sp + 2 + i) % 12];
            accO[i] = fma2(x, kE.y, accO[i]);
            accE[i] = fma2(x, kO.y, accE[i]);
        }
    }
    #undef LD2

    // ---- epilogue: even = accE + bl + lo(A2[8j+i+32])*k63, odd = accO ----
    float4* orow = (float4*)(out + (size_t)b * WLEN + 16 * j);
    #pragma unroll
    for (int p = 0; p < 4; p++) {
        float4 r;
        #pragma unroll
        for (int h = 0; h < 2; h++) {
            const int i = 2 * p + h;
            float ex, ey, ox, oy, tx, ty;
            unpk(accE[i], ex, ey);
            unpk(accO[i], ox, oy);
            unpk(v[(32 + i) % 12], tx, ty);    // A2[8j+i+32] (slots 8,9,10,11,0,1,2,3)
            float e = (ex + ey) + bl[i] + tx * k63;
            float o = ox + oy;
            if (h == 0) { r.x = e; r.y = o; } else { r.z = e; r.w = o; }
        }
        orow[p] = r;
    }
}

extern "C" void kernel_launch(void* const* d_in, const int* in_sizes, int n_in,
                              void* d_out, int out_size) {
    const float* dk  = (const float*)d_in[0];
    const float* irf = (const float*)d_in[1];
    float* out = (float*)d_out;
    int B = in_sizes[1] / TLEN;   // irf has B*64 elements
    irf_reconv_kernel<<<B, NTH>>>(dk, irf, out);
}

// round 4
// speedup vs baseline: 1.9524x; 1.0681x over previous
#include <cuda_runtime.h>

// out[b,w] = sum_{t=0}^{63} dk[b, w+t-31] * k[b,t],  k = irf / max(irf, axis=1)
// B = 16384, W = 2048, T = 64. One block (128 threads) per row; 16 outputs/thread.
//
// Af[i] = dk[i-32] for i in [32,2080), 0 elsewhere. A2[m] = (Af[2m], Af[2m+1]).
// Storage pitch-pad: p(m) = m + (m>>3)  (conflict-free 2-wavefront LDS.64).
//
// out[w] = sum_t Af[w+1+t] * k[t]:
//   odd  w=2u+1: Σ_{s=0..31} A2[u+1+s] . K2[s],   K2[s]  = (k[2s], k[2s+1])
//   even w=2u  : Af[2u+1]k0 + Σ_{s=0..30} A2[u+1+s] . K2o[s] + Af[2u+64]k63
//                K2o[s] = (k[2s+1], k[2s+2]),  K2o[31] = (0,0)
//
// Mainloop: 12-deep register ring (v prefetch distance = 1 iteration) AND the
// k-pair LDS.128 loads software-pipelined one iteration ahead. Boundary term
// Af[2u+1]k0 folded into accE init via one FFMA2 with (0, k0).

#define WLEN 2048
#define TLEN 64
#define NTH  128
#define NF2PAD 1190

typedef unsigned long long u64;

__device__ __forceinline__ u64 fma2(u64 a, u64 b, u64 c) {
    u64 d;
    asm("fma.rn.f32x2 %0, %1, %2, %3;" : "=l"(d) : "l"(a), "l"(b), "l"(c));
    return d;
}
__device__ __forceinline__ void unpk(u64 a, float& x, float& y) {
    asm("mov.b64 {%0, %1}, %2;" : "=f"(x), "=f"(y) : "l"(a));
}
__device__ __forceinline__ u64 pk(float x, float y) {
    u64 d;
    asm("mov.b64 %0, {%1, %2};" : "=l"(d) : "f"(x), "f"(y));
    return d;
}

__global__ __launch_bounds__(NTH)
void irf_reconv_kernel(const float* __restrict__ dk,
                       const float* __restrict__ irf,
                       float* __restrict__ out) {
    __shared__ __align__(16) float sA[NF2PAD * 2];
    __shared__ __align__(16) float sK[64];    // K2[s]  = (k[2s], k[2s+1])
    __shared__ __align__(16) float sKo[64];   // K2o[s] = (k[2s+1], k[2s+2]); K2o[31]=(0,0)

    const int b   = blockIdx.x;
    const int tid = threadIdx.x;
    float2* s2 = (float2*)sA;

    // ---- warp 0: normalize kernel + build shifted copy ----
    if (tid < 32) {
        float a0 = irf[(size_t)b * TLEN + 2 * tid];
        float a1 = irf[(size_t)b * TLEN + 2 * tid + 1];
        float m = fmaxf(a0, a1);
        #pragma unroll
        for (int o = 16; o > 0; o >>= 1)
            m = fmaxf(m, __shfl_xor_sync(0xffffffffu, m, o));
        float k0v = a0 / m, k1v = a1 / m;
        sK[2 * tid]     = k0v;
        sK[2 * tid + 1] = k1v;
        float nxt = __shfl_down_sync(0xffffffffu, k0v, 1);   // k[2t+2]
        bool last = (tid == 31);
        sKo[2 * tid]     = last ? 0.0f : k1v;
        sKo[2 * tid + 1] = last ? 0.0f : nxt;
    }

    // ---- zero halo: A2[0..15] and A2[1040..1057] ----
    if (tid < 34) {
        int m = (tid < 16) ? tid : (1040 + tid - 16);
        s2[m + (m >> 3)] = make_float2(0.0f, 0.0f);
    }

    // ---- fill interior: coalesced LDG.128, pair-contiguous STS.64 ----
    {
        const float4* drow = (const float4*)(dk + (size_t)b * WLEN);
        #pragma unroll
        for (int t = 0; t < 4; t++) {
            int q = tid + t * NTH;
            float4 d = drow[q];
            int m0 = 2 * q + 16;
            int p0 = m0 + (m0 >> 3);
            s2[p0]     = make_float2(d.x, d.y);
            s2[p0 + 1] = make_float2(d.z, d.w);
        }
    }
    __syncthreads();

    // ---- main compute: thread j owns u = 8j+i  (w = 16j+2i, 16j+2i+1) ----
    const int j = tid;
    const float* base = sA + 18 * j;
    #define LD2(m) (*(const u64*)(base + 2 * ((m) + ((m) >> 3))))

    u64 v[12];                                 // v[m % 12] = A2[8j + m]
    #pragma unroll
    for (int m = 0; m < 10; m++) v[m] = LD2(m);

    const float k0  = sK[0];
    const float k63 = sK[63];
    const u64 kInit = pk(0.0f, k0);            // (0, k0)

    u64 accE[8], accO[8];
    #pragma unroll
    for (int i = 0; i < 8; i++) {
        accE[i] = fma2(v[i], kInit, 0ull);     // (0, Af[2u+1]*k0)
        accO[i] = 0ull;
    }

    // software-pipelined k pairs
    ulonglong2 kEc = *(const ulonglong2*)&sK [0];
    ulonglong2 kOc = *(const ulonglong2*)&sKo[0];

    #pragma unroll
    for (int sp = 0; sp < 16; sp++) {
        // prefetch next iteration's k pairs (consumed 16 FFMA2 later)
        ulonglong2 kEn, kOn;
        if (sp < 15) {
            kEn = *(const ulonglong2*)&sK [4 * (sp + 1)];
            kOn = *(const ulonglong2*)&sKo[4 * (sp + 1)];
        }
        // prefetch v positions 2sp+10, 2sp+11 (consumed next iteration)
        v[(2 * sp + 10) % 12] = LD2(2 * sp + 10);
        v[(2 * sp + 11) % 12] = LD2(2 * sp + 11);

        #pragma unroll
        for (int i = 0; i < 8; i++) {          // tap 2sp: positions 2sp+1+i
            u64 x = v[(2 * sp + 1 + i) % 12];
            accO[i] = fma2(x, kEc.x, accO[i]);
            accE[i] = fma2(x, kOc.x, accE[i]);
        }
        #pragma unroll
        for (int i = 0; i < 8; i++) {          // tap 2sp+1: positions 2sp+2+i
            u64 x = v[(2 * sp + 2 + i) % 12];
            accO[i] = fma2(x, kEc.y, accO[i]);
            accE[i] = fma2(x, kOc.y, accE[i]);
        }
        if (sp < 15) { kEc = kEn; kOc = kOn; }
    }
    #undef LD2

    // ---- epilogue: even = lo+hi(accE) + lo(A2[u+32])*k63, odd = lo+hi(accO) ----
    float4* orow = (float4*)(out + (size_t)b * WLEN + 16 * j);
    #pragma unroll
    for (int p = 0; p < 4; p++) {
        float4 r;
        #pragma unroll
        for (int h = 0; h < 2; h++) {
            const int i = 2 * p + h;
            float ex, ey, ox, oy, tx, ty;
            unpk(accE[i], ex, ey);
            unpk(accO[i], ox, oy);
            unpk(v[(32 + i) % 12], tx, ty);    // A2[8j+i+32]
            float e = (ex + ey) + tx * k63;
            float o = ox + oy;
            if (h == 0) { r.x = e; r.y = o; } else { r.z = e; r.w = o; }
        }
        orow[p] = r;
    }
}

extern "C" void kernel_launch(void* const* d_in, const int* in_sizes, int n_in,
                              void* d_out, int out_size) {
    const float* dk  = (const float*)d_in[0];
    const float* irf = (const float*)d_in[1];
    float* out = (float*)d_out;
    int B = in_sizes[1] / TLEN;   // irf has B*64 elements
    irf_reconv_kernel<<<B, NTH>>>(dk, irf, out);
}